// round 1
// baseline (speedup 1.0000x reference)
#include <cuda_runtime.h>

#define NN 8000000
#define TPB 256
// N/4 threads = 2,000,000 ; blocks = ceil(2e6/256) = 7813
#define NBLK 7813

__device__ float g_partials[NBLK];

__device__ __forceinline__ float limiter_f(float a, float b) {
    // Reference's where-branches are dead code: idx1 & idx2 is always False,
    // so the limiter is just min(0.5*|a+b|, 2*min(|a|,|b|)).
    return fminf(0.5f * fabsf(a + b), 2.0f * fminf(fabsf(a), fabsf(b)));
}

__global__ __launch_bounds__(TPB) void net_main(
    const float* __restrict__ y, const float* __restrict__ gsyn,
    const float* __restrict__ Isyn, float* __restrict__ out)
{
    const float GL = 0.1f, EL = -5.0f, Cm = 0.3f, IEXT = 0.4f;
    const float INV_DTS = 2.0f;           // 1/0.5 exact
    const float COEF = 0.4f;              // 0.5*(1 - DT/DTS)
    const float INV_S = 0.57735026918962576f; // 1/(SIGMA*sqrt(2)) = 1/sqrt(3)
    const float SQ2 = 1.41421356237309505f;
    const float SQ2PI = 0.7978845608028654f;

    int tid = blockIdx.x * TPB + threadIdx.x;
    int i0 = tid * 4;

    float gs = gsyn[0];
    float Is = Isyn[0];
    float tau_m = Cm / (GL + gs);
    float inv_tau = (GL + gs) / Cm;

    float lsum = 0.0f;

    if (i0 < NN) {
        const float* ro = y;
        const float* V  = y + NN;

        float4 r4 = *reinterpret_cast<const float4*>(ro + i0);
        float4 v4 = *reinterpret_cast<const float4*>(V + i0);

        float r[7], v[7];
        r[0] = (i0 >= 2)      ? ro[i0 - 2] : 0.0f;
        r[1] = (i0 >= 1)      ? ro[i0 - 1] : 0.0f;
        r[2] = r4.x; r[3] = r4.y; r[4] = r4.z; r[5] = r4.w;
        r[6] = (i0 + 4 < NN)  ? ro[i0 + 4] : 0.0f;
        v[0] = (i0 >= 2)      ? V[i0 - 2]  : 0.0f;
        v[1] = (i0 >= 1)      ? V[i0 - 1]  : 0.0f;
        v[2] = v4.x; v[3] = v4.y; v[4] = v4.z; v[5] = v4.w;
        v[6] = (i0 + 4 < NN)  ? V[i0 + 4]  : 0.0f;

        float oro[4], ov[4];

        #pragma unroll
        for (int k = 0; k < 4; k++) {
            int i = i0 + k;
            float Vi  = v[k + 2];
            float roi = r[k + 2];

            float dVdt = (GL * (EL - Vi) + IEXT + Is) / Cm;

            // H function
            float dV_ = fmaxf(-Vi, -1.0f);        // VT = 0
            float T   = dV_ * INV_S;
            float T2  = T * T;
            float p   = 0.0061f + T * (-1.12f + T * (-0.257f + T * (-0.072f + T * (-0.0117f))));
            float A   = expf(p);
            float dTdt = fminf(-dVdt * INV_S, 0.0f);
            float F_T  = SQ2PI * expf(-T2) / (1.00000001f + erff(T));
            float B    = -SQ2 * dTdt * F_T * tau_m;
            float H    = fmaxf((A + B) * inv_tau, 0.0f);
            float src  = roi * H;
            lsum += src;

            // ---- dro_dt (stencil on ro, source = src) ----
            {
                float dz0 = r[k + 1] - r[k];
                float dz1 = r[k + 2] - r[k + 1];
                float dz2 = r[k + 3] - r[k + 2];
                float val;
                if (i == 0) {
                    val = -roi * INV_DTS;          // + firing patched by fix kernel
                } else if (i == NN - 1) {
                    val = (r[k + 1] + COEF * limiter_f(dz1, dz0)) * INV_DTS - src;
                } else {
                    float wi  = limiter_f(dz2, dz1);
                    float wi1 = (i == 1) ? 0.0f : limiter_f(dz1, dz0);
                    val = -(dz1 + COEF * (wi - wi1)) * INV_DTS - src;
                }
                oro[k] = val;
            }

            // ---- dV_dt (stencil on V, source = -dVdt; endpoints overridden) ----
            {
                float e0 = v[k + 1] - v[k];
                float e1 = v[k + 2] - v[k + 1];
                float e2 = v[k + 3] - v[k + 2];
                float val;
                if (i == 0) {
                    val = 0.0f;
                } else if (i == NN - 1) {
                    val = dVdt;
                } else {
                    float wi  = limiter_f(e2, e1);
                    float wi1 = (i == 1) ? 0.0f : limiter_f(e1, e0);
                    val = -(e1 + COEF * (wi - wi1)) * INV_DTS + dVdt;
                }
                ov[k] = val;
            }
        }

        *reinterpret_cast<float4*>(out + i0)      = make_float4(oro[0], oro[1], oro[2], oro[3]);
        *reinterpret_cast<float4*>(out + NN + i0) = make_float4(ov[0],  ov[1],  ov[2],  ov[3]);
    }

    // Deterministic block reduction of src partial sums
    __shared__ float ssum[TPB];
    ssum[threadIdx.x] = lsum;
    __syncthreads();
    #pragma unroll
    for (int s = TPB / 2; s > 0; s >>= 1) {
        if (threadIdx.x < s) ssum[threadIdx.x] += ssum[threadIdx.x + s];
        __syncthreads();
    }
    if (threadIdx.x == 0) g_partials[blockIdx.x] = ssum[0];
}

__global__ __launch_bounds__(256) void net_fix(
    const float* __restrict__ y, float* __restrict__ out)
{
    __shared__ float ssum[256];
    float s = 0.0f;
    for (int i = threadIdx.x; i < NBLK; i += 256) s += g_partials[i];
    ssum[threadIdx.x] = s;
    __syncthreads();
    #pragma unroll
    for (int st = 128; st > 0; st >>= 1) {
        if (threadIdx.x < st) ssum[threadIdx.x] += ssum[threadIdx.x + st];
        __syncthreads();
    }
    if (threadIdx.x == 0) {
        // out[0] = -ro[0]/DTS - src[0],  src[0] = -firing
        out[0] = -y[0] * 2.0f + ssum[0];
    }
}

extern "C" void kernel_launch(void* const* d_in, const int* in_sizes, int n_in,
                              void* d_out, int out_size) {
    // inputs: t (1), y (2N), gsyn (1), Isyn (1)
    const float* y    = (const float*)d_in[1];
    const float* gsyn = (const float*)d_in[2];
    const float* Isyn = (const float*)d_in[3];
    float* out = (float*)d_out;

    net_main<<<NBLK, TPB>>>(y, gsyn, Isyn, out);
    net_fix<<<1, 256>>>(y, out);
}

// round 2
// speedup vs baseline: 1.0995x; 1.0995x over previous
#include <cuda_runtime.h>

#define NN 8000000
#define TPB 256
// N/4 threads = 2,000,000 ; blocks = ceil(2e6/256) = 7813
#define NBLK 7813

__device__ float g_partials[NBLK];
__device__ unsigned int g_count;   // zero-init; self-resets every launch

__device__ __forceinline__ float limiter_f(float a, float b) {
    // Reference's where-branches are dead code: idx1 & idx2 is always False,
    // so the limiter is just min(0.5*|a+b|, 2*min(|a|,|b|)).
    return fminf(0.5f * fabsf(a + b), 2.0f * fminf(fabsf(a), fabsf(b)));
}

__global__ __launch_bounds__(TPB) void net_main(
    const float* __restrict__ y, const float* __restrict__ gsyn,
    const float* __restrict__ Isyn, float* __restrict__ out)
{
    const float GL = 0.1f, EL = -5.0f, Cm = 0.3f, IEXT = 0.4f;
    const float INV_DTS = 2.0f;               // 1/0.5 exact
    const float COEF = 0.4f;                  // 0.5*(1 - DT/DTS)
    const float INV_S = 0.57735026918962576f; // 1/(SIGMA*sqrt(2)) = 1/sqrt(3)
    const float SQ2 = 1.41421356237309505f;
    const float SQ2PI = 0.7978845608028654f;

    int tid = blockIdx.x * TPB + threadIdx.x;
    int i0 = tid * 4;

    float gs = gsyn[0];
    float Is = Isyn[0];
    float tau_m = Cm / (GL + gs);
    float inv_tau = (GL + gs) / Cm;

    float lsum = 0.0f;

    if (i0 < NN) {
        const float* ro = y;
        const float* V  = y + NN;

        float4 r4 = *reinterpret_cast<const float4*>(ro + i0);
        float4 v4 = *reinterpret_cast<const float4*>(V + i0);

        float r[7], v[7];
        r[0] = (i0 >= 2)      ? ro[i0 - 2] : 0.0f;
        r[1] = (i0 >= 1)      ? ro[i0 - 1] : 0.0f;
        r[2] = r4.x; r[3] = r4.y; r[4] = r4.z; r[5] = r4.w;
        r[6] = (i0 + 4 < NN)  ? ro[i0 + 4] : 0.0f;
        v[0] = (i0 >= 2)      ? V[i0 - 2]  : 0.0f;
        v[1] = (i0 >= 1)      ? V[i0 - 1]  : 0.0f;
        v[2] = v4.x; v[3] = v4.y; v[4] = v4.z; v[5] = v4.w;
        v[6] = (i0 + 4 < NN)  ? V[i0 + 4]  : 0.0f;

        float oro[4], ov[4];

        #pragma unroll
        for (int k = 0; k < 4; k++) {
            int i = i0 + k;
            float Vi  = v[k + 2];
            float roi = r[k + 2];

            float dVdt = (GL * (EL - Vi) + IEXT + Is) / Cm;

            // H function (fast-math variants: tolerance is 1e-3, we are ~1e-6)
            float dV_ = fmaxf(-Vi, -1.0f);        // VT = 0
            float T   = dV_ * INV_S;
            float T2  = T * T;
            float p   = 0.0061f + T * (-1.12f + T * (-0.257f + T * (-0.072f + T * (-0.0117f))));
            float A   = __expf(p);
            float dTdt = fminf(-dVdt * INV_S, 0.0f);
            float F_T  = SQ2PI * __fdividef(__expf(-T2), 1.00000001f + erff(T));
            float B    = -SQ2 * dTdt * F_T * tau_m;
            float H    = fmaxf((A + B) * inv_tau, 0.0f);
            float src  = roi * H;
            lsum += src;

            // ---- dro_dt (stencil on ro, source = src) ----
            {
                float dz0 = r[k + 1] - r[k];
                float dz1 = r[k + 2] - r[k + 1];
                float dz2 = r[k + 3] - r[k + 2];
                float val;
                if (i == 0) {
                    val = 0.0f;                    // written by last block instead
                } else if (i == NN - 1) {
                    val = (r[k + 1] + COEF * limiter_f(dz1, dz0)) * INV_DTS - src;
                } else {
                    float wi  = limiter_f(dz2, dz1);
                    float wi1 = (i == 1) ? 0.0f : limiter_f(dz1, dz0);
                    val = -(dz1 + COEF * (wi - wi1)) * INV_DTS - src;
                }
                oro[k] = val;
            }

            // ---- dV_dt (stencil on V, source = -dVdt; endpoints overridden) ----
            {
                float e0 = v[k + 1] - v[k];
                float e1 = v[k + 2] - v[k + 1];
                float e2 = v[k + 3] - v[k + 2];
                float val;
                if (i == 0) {
                    val = 0.0f;
                } else if (i == NN - 1) {
                    val = dVdt;
                } else {
                    float wi  = limiter_f(e2, e1);
                    float wi1 = (i == 1) ? 0.0f : limiter_f(e1, e0);
                    val = -(e1 + COEF * (wi - wi1)) * INV_DTS + dVdt;
                }
                ov[k] = val;
            }
        }

        if (i0 == 0) {
            // leave out[0] for the last block (avoids same-address race)
            out[1] = oro[1]; out[2] = oro[2]; out[3] = oro[3];
        } else {
            *reinterpret_cast<float4*>(out + i0) = make_float4(oro[0], oro[1], oro[2], oro[3]);
        }
        *reinterpret_cast<float4*>(out + NN + i0) = make_float4(ov[0], ov[1], ov[2], ov[3]);
    }

    // ---- warp-shuffle reduction of src partial sums ----
    #pragma unroll
    for (int off = 16; off > 0; off >>= 1)
        lsum += __shfl_down_sync(0xFFFFFFFFu, lsum, off);

    __shared__ float wsum[TPB / 32];
    int lane = threadIdx.x & 31;
    int warp = threadIdx.x >> 5;
    if (lane == 0) wsum[warp] = lsum;
    __syncthreads();

    if (warp == 0) {
        float s = (lane < TPB / 32) ? wsum[lane] : 0.0f;
        #pragma unroll
        for (int off = 4; off > 0; off >>= 1)
            s += __shfl_down_sync(0xFFFFFFFFu, s, off);
        if (lane == 0) g_partials[blockIdx.x] = s;
    }

    // ---- last block finishes the global reduction and writes out[0] ----
    __shared__ bool isLast;
    if (threadIdx.x == 0) {
        __threadfence();
        unsigned int v = atomicAdd(&g_count, 1u);
        isLast = (v == NBLK - 1);
    }
    __syncthreads();

    if (isLast) {
        float s = 0.0f;
        for (int i = threadIdx.x; i < NBLK; i += TPB) s += g_partials[i];
        #pragma unroll
        for (int off = 16; off > 0; off >>= 1)
            s += __shfl_down_sync(0xFFFFFFFFu, s, off);
        if ((threadIdx.x & 31) == 0) wsum[threadIdx.x >> 5] = s;
        __syncthreads();
        if (threadIdx.x < 32) {
            float t = (threadIdx.x < TPB / 32) ? wsum[threadIdx.x] : 0.0f;
            #pragma unroll
            for (int off = 4; off > 0; off >>= 1)
                t += __shfl_down_sync(0xFFFFFFFFu, t, off);
            if (threadIdx.x == 0) {
                // out[0] = -ro[0]/DTS - src[0],  src[0] = -firing
                out[0] = -y[0] * 2.0f + t;
                g_count = 0u;    // self-reset for next graph replay
            }
        }
    }
}

extern "C" void kernel_launch(void* const* d_in, const int* in_sizes, int n_in,
                              void* d_out, int out_size) {
    // inputs: t (1), y (2N), gsyn (1), Isyn (1)
    const float* y    = (const float*)d_in[1];
    const float* gsyn = (const float*)d_in[2];
    const float* Isyn = (const float*)d_in[3];
    float* out = (float*)d_out;

    net_main<<<NBLK, TPB>>>(y, gsyn, Isyn, out);
}

// round 3
// speedup vs baseline: 1.2815x; 1.1655x over previous
#include <cuda_runtime.h>

#define NN 8000000
#define TPB 256
// N/4 threads = 2,000,000 ; blocks = ceil(2e6/256) = 7813
#define NBLK 7813

__device__ float g_partials[NBLK];
__device__ unsigned int g_count;   // zero-init; self-resets every launch

__device__ __forceinline__ float ex2f_(float x){ float r; asm("ex2.approx.ftz.f32 %0, %1;":"=f"(r):"f"(x)); return r; }
__device__ __forceinline__ float sqrtf_(float x){ float r; asm("sqrt.approx.ftz.f32 %0, %1;":"=f"(r):"f"(x)); return r; }
__device__ __forceinline__ float rcpf_(float x){ float r; asm("rcp.approx.ftz.f32 %0, %1;":"=f"(r):"f"(x)); return r; }

#define LOG2E  1.442695040888963f
#define INV_S  0.57735026918962576f   // 1/(SIGMA*sqrt(2)) = 1/sqrt(3)
#define CERF   1.1283791670955126f    // 2/sqrt(pi) = SQ2*SQ2PI
#define DKC    0.6514700059f          // INV_S * CERF
// exp(p) coefficients pre-scaled by LOG2E so A = 2^poly
#define C0 0.0088004397f              // 0.0061   * LOG2E
#define C1 (-1.6158184f)              // -1.12    * LOG2E
#define C2 (-0.37077263f)             // -0.257   * LOG2E
#define C3 (-0.10387404f)             // -0.072   * LOG2E
#define C4 (-0.016879532f)            // -0.0117  * LOG2E

// doubled limiter: 2*L(a,b) = min(|a+b|, 4*min(|a|,|b|))
// (reference's where-branches are dead code; L = min(0.5|a+b|, 2min(|a|,|b|)))
__device__ __forceinline__ float lim2(float a, float b){
    return fminf(fabsf(a + b), 4.0f * fminf(fabsf(a), fabsf(b)));
}

// H(V); also outputs dVdt. All tau_m/constant factors pre-folded.
__device__ __forceinline__ float Hfun(float Vi, float dv_a, float dv_b,
                                      float inv_tau, float& dVdt)
{
    dVdt    = fmaf(dv_b, Vi, dv_a);
    float T = fmaxf(-Vi, -1.0f) * INV_S;             // VT = 0
    float dK = fmaxf(dVdt * DKC, 0.0f);              // = -CERF * dT_dt
    float T2 = T * T;
    float E  = ex2f_(-LOG2E * T2);                   // exp(-T^2)
    float s  = sqrtf_(T2 + 1.7f);                    // erfcx asymptotic
    float w  = rcpf_(T + s);
    float denom = fmaf(-CERF, E * w, 2.00000001f);   // 1.00000001 + erf(T)
    float poly  = fmaf(fmaf(fmaf(fmaf(C4, T, C3), T, C2), T, C1), T, C0);
    float A  = ex2f_(poly);                          // exp(p(T))
    float rd = rcpf_(denom);
    float t  = dK * E * rd;                          // B / tau_m
    return fmaxf(fmaf(A, inv_tau, t), 0.0f);
}

__global__ __launch_bounds__(TPB) void net_main(
    const float* __restrict__ y, const float* __restrict__ gsyn,
    const float* __restrict__ Isyn, float* __restrict__ out)
{
    int tid = blockIdx.x * TPB + threadIdx.x;
    int i0 = tid * 4;

    float gs = gsyn[0];
    float Is = Isyn[0];
    const float inv_cm = 3.3333333f;                 // 1/0.3
    float dv_a = (0.1f * (-5.0f) + 0.4f + Is) * inv_cm;
    const float dv_b = -0.33333334f;                 // -GL/Cm
    float inv_tau = (0.1f + gs) * inv_cm;

    const float* ro = y;
    const float* V  = y + NN;
    float lsum = 0.0f;

    bool edge = (blockIdx.x == 0) || (blockIdx.x == NBLK - 1);

    if (!edge) {
        // ---------------- fast interior path: no per-element predicates ----------
        float4 r4 = *reinterpret_cast<const float4*>(ro + i0);
        float4 v4 = *reinterpret_cast<const float4*>(V + i0);
        float vv[4] = {v4.x, v4.y, v4.z, v4.w};
        float rr[4] = {r4.x, r4.y, r4.z, r4.w};

        float src[4], dvdt[4];
        #pragma unroll
        for (int k = 0; k < 4; k++) {
            float H = Hfun(vv[k], dv_a, dv_b, inv_tau, dvdt[k]);
            src[k] = rr[k] * H;
            lsum += src[k];
        }

        // ro stencil (shared limiters across the 4 elements)
        {
            float a[7];
            a[0] = ro[i0 - 2]; a[1] = ro[i0 - 1];
            a[2] = r4.x; a[3] = r4.y; a[4] = r4.z; a[5] = r4.w;
            a[6] = ro[i0 + 4];
            float D[6];
            #pragma unroll
            for (int j = 0; j < 6; j++) D[j] = a[j + 1] - a[j];
            float W[5];
            #pragma unroll
            for (int j = 0; j < 5; j++) W[j] = lim2(D[j + 1], D[j]);
            float o[4];
            #pragma unroll
            for (int k = 0; k < 4; k++)
                o[k] = fmaf(-2.0f, D[k + 1], fmaf(-0.4f, W[k + 1] - W[k], -src[k]));
            *reinterpret_cast<float4*>(out + i0) = make_float4(o[0], o[1], o[2], o[3]);
        }
        // V stencil
        {
            float a[7];
            a[0] = V[i0 - 2]; a[1] = V[i0 - 1];
            a[2] = v4.x; a[3] = v4.y; a[4] = v4.z; a[5] = v4.w;
            a[6] = V[i0 + 4];
            float D[6];
            #pragma unroll
            for (int j = 0; j < 6; j++) D[j] = a[j + 1] - a[j];
            float W[5];
            #pragma unroll
            for (int j = 0; j < 5; j++) W[j] = lim2(D[j + 1], D[j]);
            float o[4];
            #pragma unroll
            for (int k = 0; k < 4; k++)
                o[k] = fmaf(-2.0f, D[k + 1], fmaf(-0.4f, W[k + 1] - W[k], dvdt[k]));
            *reinterpret_cast<float4*>(out + NN + i0) = make_float4(o[0], o[1], o[2], o[3]);
        }
    } else if (i0 < NN) {
        // ---------------- edge path (blocks 0 and NBLK-1 only) -------------------
        float r[7], v[7];
        r[0] = (i0 >= 2)     ? ro[i0 - 2] : 0.0f;
        r[1] = (i0 >= 1)     ? ro[i0 - 1] : 0.0f;
        float4 r4 = *reinterpret_cast<const float4*>(ro + i0);
        float4 v4 = *reinterpret_cast<const float4*>(V + i0);
        r[2] = r4.x; r[3] = r4.y; r[4] = r4.z; r[5] = r4.w;
        r[6] = (i0 + 4 < NN) ? ro[i0 + 4] : 0.0f;
        v[0] = (i0 >= 2)     ? V[i0 - 2]  : 0.0f;
        v[1] = (i0 >= 1)     ? V[i0 - 1]  : 0.0f;
        v[2] = v4.x; v[3] = v4.y; v[4] = v4.z; v[5] = v4.w;
        v[6] = (i0 + 4 < NN) ? V[i0 + 4]  : 0.0f;

        float oro[4], ov[4];
        #pragma unroll
        for (int k = 0; k < 4; k++) {
            int i = i0 + k;
            float dVdt;
            float H = Hfun(v[k + 2], dv_a, dv_b, inv_tau, dVdt);
            float src = r[k + 2] * H;
            lsum += src;

            {   // dro_dt
                float dz0 = r[k + 1] - r[k];
                float dz1 = r[k + 2] - r[k + 1];
                float dz2 = r[k + 3] - r[k + 2];
                float val;
                if (i == 0) {
                    val = 0.0f;                       // written by last block
                } else if (i == NN - 1) {
                    // (z[N-2] + COEF*wi)/DTS - src ; wi = lim2/2, COEF=0.4, 1/DTS=2
                    val = fmaf(0.4f, lim2(dz1, dz0), 2.0f * r[k + 1]) - src;
                } else {
                    float w1 = lim2(dz2, dz1);
                    float w0 = (i == 1) ? 0.0f : lim2(dz1, dz0);
                    val = fmaf(-2.0f, dz1, fmaf(-0.4f, w1 - w0, -src));
                }
                oro[k] = val;
            }
            {   // dV_dt
                float e0 = v[k + 1] - v[k];
                float e1 = v[k + 2] - v[k + 1];
                float e2 = v[k + 3] - v[k + 2];
                float val;
                if (i == 0) {
                    val = 0.0f;
                } else if (i == NN - 1) {
                    val = dVdt;
                } else {
                    float w1 = lim2(e2, e1);
                    float w0 = (i == 1) ? 0.0f : lim2(e1, e0);
                    val = fmaf(-2.0f, e1, fmaf(-0.4f, w1 - w0, dVdt));
                }
                ov[k] = val;
            }
        }

        if (i0 == 0) {
            // leave out[0] for the last block (avoids same-address race)
            out[1] = oro[1]; out[2] = oro[2]; out[3] = oro[3];
        } else {
            *reinterpret_cast<float4*>(out + i0) = make_float4(oro[0], oro[1], oro[2], oro[3]);
        }
        *reinterpret_cast<float4*>(out + NN + i0) = make_float4(ov[0], ov[1], ov[2], ov[3]);
    }

    // ---- warp-shuffle reduction of src partial sums ----
    #pragma unroll
    for (int off = 16; off > 0; off >>= 1)
        lsum += __shfl_down_sync(0xFFFFFFFFu, lsum, off);

    __shared__ float wsum[TPB / 32];
    int lane = threadIdx.x & 31;
    int warp = threadIdx.x >> 5;
    if (lane == 0) wsum[warp] = lsum;
    __syncthreads();

    if (warp == 0) {
        float s = (lane < TPB / 32) ? wsum[lane] : 0.0f;
        #pragma unroll
        for (int off = 4; off > 0; off >>= 1)
            s += __shfl_down_sync(0xFFFFFFFFu, s, off);
        if (lane == 0) g_partials[blockIdx.x] = s;
    }

    // ---- last block finishes the global reduction and writes out[0] ----
    __shared__ bool isLast;
    if (threadIdx.x == 0) {
        __threadfence();
        unsigned int vcnt = atomicAdd(&g_count, 1u);
        isLast = (vcnt == NBLK - 1);
    }
    __syncthreads();

    if (isLast) {
        float s = 0.0f;
        for (int i = threadIdx.x; i < NBLK; i += TPB) s += g_partials[i];
        #pragma unroll
        for (int off = 16; off > 0; off >>= 1)
            s += __shfl_down_sync(0xFFFFFFFFu, s, off);
        if ((threadIdx.x & 31) == 0) wsum[threadIdx.x >> 5] = s;
        __syncthreads();
        if (threadIdx.x < 32) {
            float t = (threadIdx.x < TPB / 32) ? wsum[threadIdx.x] : 0.0f;
            #pragma unroll
            for (int off = 4; off > 0; off >>= 1)
                t += __shfl_down_sync(0xFFFFFFFFu, t, off);
            if (threadIdx.x == 0) {
                // out[0] = -ro[0]/DTS - src[0],  src[0] = -firing
                out[0] = -y[0] * 2.0f + t;
                g_count = 0u;    // self-reset for next graph replay
            }
        }
    }
}

extern "C" void kernel_launch(void* const* d_in, const int* in_sizes, int n_in,
                              void* d_out, int out_size) {
    // inputs: t (1), y (2N), gsyn (1), Isyn (1)
    const float* y    = (const float*)d_in[1];
    const float* gsyn = (const float*)d_in[2];
    const float* Isyn = (const float*)d_in[3];
    float* out = (float*)d_out;

    net_main<<<NBLK, TPB>>>(y, gsyn, Isyn, out);
}